// round 2
// baseline (speedup 1.0000x reference)
#include <cuda_runtime.h>
#include <math.h>

#define NNODE 20000
#define NEDGE 160000
#define E2    320000
#define HH    128
#define NF    16
#define EF    16

// ---------------- device scratch (no allocations allowed) ----------------
__device__ int   g_deg[NNODE];
__device__ int   g_rowoff[NNODE];
__device__ int   g_cursor[NNODE];
__device__ float g_dis[NNODE];
__device__ int   g_csr_src[E2];
__device__ int   g_csr_eid[E2];
__device__ float g_h0[NNODE * NF];
__device__ float g_nb[4][NNODE * HH];          // node-feature ping-pong buffers
__device__ float g_msg[(size_t)E2 * HH];       // edge message buffer (164 MB)

__device__ __forceinline__ float* nodebuf(int s) { return g_nb[s]; }

// ---------------- graph structure build ----------------
__global__ void k_zero() {
    int i = blockIdx.x * 256 + threadIdx.x;
    if (i < NNODE) g_deg[i] = 0;
}

__global__ void k_hist(const int* __restrict__ ei) {
    int e = blockIdx.x * 256 + threadIdx.x;
    if (e >= E2) return;
    int d = (e < NEDGE) ? ei[NEDGE + e] : ei[e - NEDGE];
    atomicAdd(&g_deg[d], 1);
}

// single-block exclusive scan over degrees; also rsqrt norm + cursor init
__global__ void k_scan() {
    __shared__ int s[1024];
    __shared__ int carry;
    int t = threadIdx.x;
    if (t == 0) carry = 0;
    __syncthreads();
    for (int base = 0; base < NNODE; base += 1024) {
        int i = base + t;
        int v = (i < NNODE) ? g_deg[i] : 0;
        int cprev = carry;
        s[t] = v;
        __syncthreads();
        for (int off = 1; off < 1024; off <<= 1) {
            int add = (t >= off) ? s[t - off] : 0;
            __syncthreads();
            s[t] += add;
            __syncthreads();
        }
        if (i < NNODE) {
            int excl = s[t] - v + cprev;
            g_rowoff[i] = excl;
            g_cursor[i] = excl;
            g_dis[i] = (v > 0) ? rsqrtf((float)v) : 0.f;
        }
        __syncthreads();
        if (t == 0) carry = cprev + s[1023];
        __syncthreads();
    }
}

__global__ void k_scatter(const int* __restrict__ ei) {
    int e = blockIdx.x * 256 + threadIdx.x;
    if (e >= E2) return;
    int srcv = ei[e];  // works for both halves: [0,E)=src row, [E,2E)=dst row reversed
    int d = (e < NEDGE) ? ei[NEDGE + e] : ei[e - NEDGE];
    int slot = atomicAdd(&g_cursor[d], 1);
    g_csr_src[slot] = srcv;
    g_csr_eid[slot] = e;
}

// ---------------- mask MLP + residual: g_h0 = mlp2(mask) + x ----------------
__global__ void __launch_bounds__(128) k_maskmlp(
    const float* __restrict__ x, const float* __restrict__ mask,
    const float* __restrict__ w1, const float* __restrict__ b1,
    const float* __restrict__ w2, const float* __restrict__ b2)
{
    constexpr int T = 16;
    __shared__ __align__(16) float sM[T * NF];
    __shared__ __align__(16) float sH[T * HH];
    int tid = threadIdx.x;
    int n0 = blockIdx.x * T;
    for (int o = tid; o < T * NF; o += 128) sM[o] = mask[n0 * NF + o];
    __syncthreads();

    float acc[T];
    float bj = b1[tid];
#pragma unroll
    for (int t = 0; t < T; t++) acc[t] = bj;
#pragma unroll
    for (int i = 0; i < NF; i += 4) {
        float wa = w1[(i + 0) * HH + tid], wb = w1[(i + 1) * HH + tid];
        float wc = w1[(i + 2) * HH + tid], wd = w1[(i + 3) * HH + tid];
#pragma unroll
        for (int t = 0; t < T; t++) {
            float4 v = *reinterpret_cast<const float4*>(&sM[t * NF + i]);
            acc[t] = fmaf(v.x, wa, acc[t]); acc[t] = fmaf(v.y, wb, acc[t]);
            acc[t] = fmaf(v.z, wc, acc[t]); acc[t] = fmaf(v.w, wd, acc[t]);
        }
    }
#pragma unroll
    for (int t = 0; t < T; t++) sH[t * HH + tid] = fmaxf(acc[t], 0.f);
    __syncthreads();

    for (int o = tid; o < T * NF; o += 128) {
        int t = o >> 4, c = o & 15;
        float v = b2[c];
#pragma unroll 1
        for (int k = 0; k < HH; k += 4) {
            float4 h = *reinterpret_cast<const float4*>(&sH[t * HH + k]);
            v = fmaf(h.x, w2[(k + 0) * NF + c], v);
            v = fmaf(h.y, w2[(k + 1) * NF + c], v);
            v = fmaf(h.z, w2[(k + 2) * NF + c], v);
            v = fmaf(h.w, w2[(k + 3) * NF + c], v);
        }
        g_h0[n0 * NF + o] = v + x[n0 * NF + o];
    }
}

// ---------------- fused edge MLP: msg[e] = relu(cat @ W1 + b1) @ W2 + b2 ----------------
template <int DH, int DOUT>
__global__ void __launch_bounds__(128) k_ea_msg(
    int hsel,
    const float* __restrict__ eattr, const int* __restrict__ ei,
    const float* __restrict__ w1, const float* __restrict__ b1,
    const float* __restrict__ w2, const float* __restrict__ b2)
{
    constexpr int T = 32;
    constexpr int DIN = 2 * DH + EF;
    constexpr int IN_F  = T * DIN;
    constexpr int HID_F = T * HH;
    constexpr int RED_F = (DOUT == 16) ? 8 * T * 16 : 0;
    constexpr int SM_F  = (IN_F > HID_F + RED_F) ? IN_F : (HID_F + RED_F);
    __shared__ __align__(16) float sm[SM_F];
    __shared__ int sSrc[T], sDst[T], sEa[T];

    const float* hfeat = (DH == NF) ? g_h0 : nodebuf(hsel);
    int tid = threadIdx.x;
    int e0 = blockIdx.x * T;
    if (tid < T) {
        int e = e0 + tid;
        sSrc[tid] = ei[e];
        sDst[tid] = (e < NEDGE) ? ei[NEDGE + e] : ei[e - NEDGE];
        sEa[tid]  = (e < NEDGE) ? e : e - NEDGE;
    }
    __syncthreads();

    // stage concatenated inputs
#pragma unroll 1
    for (int t = 0; t < T; t++) {
        int d = sDst[t], s = sSrc[t], er = sEa[t];
        for (int p = tid; p < DIN; p += 128) {
            float v;
            if (p < DH)           v = hfeat[d * DH + p];
            else if (p < 2 * DH)  v = hfeat[s * DH + (p - DH)];
            else                  v = eattr[er * EF + (p - 2 * DH)];
            sm[t * DIN + p] = v;
        }
    }
    __syncthreads();

    // hidden = relu(in @ W1 + b1); thread j owns hidden column j for 32 edges
    int j = tid;
    float acc[T];
    float bj = b1[j];
#pragma unroll
    for (int t = 0; t < T; t++) acc[t] = bj;
#pragma unroll 1
    for (int i = 0; i < DIN; i += 4) {
        float wa = w1[(i + 0) * HH + j], wb = w1[(i + 1) * HH + j];
        float wc = w1[(i + 2) * HH + j], wd = w1[(i + 3) * HH + j];
#pragma unroll
        for (int t = 0; t < T; t++) {
            float4 v = *reinterpret_cast<const float4*>(&sm[t * DIN + i]);
            acc[t] = fmaf(v.x, wa, acc[t]); acc[t] = fmaf(v.y, wb, acc[t]);
            acc[t] = fmaf(v.z, wc, acc[t]); acc[t] = fmaf(v.w, wd, acc[t]);
        }
    }
    __syncthreads();               // all reads of input region done
    float* shid = sm;              // hidden aliases the input region
#pragma unroll
    for (int t = 0; t < T; t++) shid[t * HH + j] = fmaxf(acc[t], 0.f);
    __syncthreads();

    if (DOUT == HH) {
        float cj = b2[j];
#pragma unroll
        for (int t = 0; t < T; t++) acc[t] = cj;
#pragma unroll 1
        for (int k = 0; k < HH; k += 4) {
            float wa = w2[(k + 0) * HH + j], wb = w2[(k + 1) * HH + j];
            float wc = w2[(k + 2) * HH + j], wd = w2[(k + 3) * HH + j];
#pragma unroll
            for (int t = 0; t < T; t++) {
                float4 v = *reinterpret_cast<const float4*>(&shid[t * HH + k]);
                acc[t] = fmaf(v.x, wa, acc[t]); acc[t] = fmaf(v.y, wb, acc[t]);
                acc[t] = fmaf(v.z, wc, acc[t]); acc[t] = fmaf(v.w, wd, acc[t]);
            }
        }
#pragma unroll
        for (int t = 0; t < T; t++) g_msg[(size_t)(e0 + t) * HH + j] = acc[t];
    } else {
        // DOUT = 16: split-K across 8 thread groups of 16
        int c = tid & 15;
        int seg = tid >> 4;
        float pacc[T];
#pragma unroll
        for (int t = 0; t < T; t++) pacc[t] = 0.f;
#pragma unroll 1
        for (int k = seg * 16; k < seg * 16 + 16; k += 4) {
            float wa = w2[(k + 0) * 16 + c], wb = w2[(k + 1) * 16 + c];
            float wc = w2[(k + 2) * 16 + c], wd = w2[(k + 3) * 16 + c];
#pragma unroll
            for (int t = 0; t < T; t++) {
                float4 v = *reinterpret_cast<const float4*>(&shid[t * HH + k]);
                pacc[t] = fmaf(v.x, wa, pacc[t]); pacc[t] = fmaf(v.y, wb, pacc[t]);
                pacc[t] = fmaf(v.z, wc, pacc[t]); pacc[t] = fmaf(v.w, wd, pacc[t]);
            }
        }
        float* sred = sm + HID_F;
#pragma unroll
        for (int t = 0; t < T; t++) sred[(seg * T + t) * 16 + c] = pacc[t];
        __syncthreads();
        for (int o = tid; o < T * 16; o += 128) {
            int t = o >> 4, cc = o & 15;
            float v = b2[cc];
#pragma unroll
            for (int s2 = 0; s2 < 8; s2++) v += sred[(s2 * T + t) * 16 + cc];
            g_msg[(size_t)(e0 + t) * 16 + cc] = v;
        }
    }
}

// ---------------- CSR segment-sum of messages ----------------
template <int DOUT, bool RELU>
__global__ void k_agg(float* __restrict__ outp, int outsel) {
    constexpr int PER = 128 / DOUT;
    int tid = threadIdx.x;
    int n = blockIdx.x * PER + tid / DOUT;
    int j = tid % DOUT;
    if (n >= NNODE) return;
    float* out = outp ? outp : nodebuf(outsel);
    int beg = g_rowoff[n], len = g_deg[n];
    float acc = 0.f;
    for (int i = 0; i < len; i++) {
        int eid = g_csr_eid[beg + i];
        acc += g_msg[(size_t)eid * DOUT + j];
    }
    if (RELU) acc = fmaxf(acc, 0.f);
    out[n * DOUT + j] = acc;
}

// ---------------- TAG propagation hop: out[n] = dis[n] * sum dis[s] * h[s] ----------------
__global__ void k_hop(int insel, int outsel) {
    const float* hin = nodebuf(insel);
    float* hout = nodebuf(outsel);
    int n = blockIdx.x, j = threadIdx.x;
    int beg = g_rowoff[n], len = g_deg[n];
    float acc = 0.f;
    for (int i = 0; i < len; i++) {
        int s = g_csr_src[beg + i];
        acc = fmaf(g_dis[s], hin[s * HH + j], acc);
    }
    hout[n * HH + j] = g_dis[n] * acc;
}

// ---------------- node GEMM: out (=bias | +=) in @ W, optional relu ----------------
template <bool INIT, bool RELU>
__global__ void __launch_bounds__(128) k_gemm(
    int insel, const float* __restrict__ W, const float* __restrict__ bias, int outsel)
{
    constexpr int T = 16;
    __shared__ __align__(16) float sIn[T * HH];
    const float* in = nodebuf(insel);
    float* out = nodebuf(outsel);
    int tid = threadIdx.x;
    int n0 = blockIdx.x * T;
#pragma unroll
    for (int t = 0; t < T; t++) sIn[t * HH + tid] = in[(n0 + t) * HH + tid];
    __syncthreads();
    float acc[T];
    if (INIT) {
        float b = bias[tid];
#pragma unroll
        for (int t = 0; t < T; t++) acc[t] = b;
    } else {
#pragma unroll
        for (int t = 0; t < T; t++) acc[t] = out[(n0 + t) * HH + tid];
    }
#pragma unroll 1
    for (int k = 0; k < HH; k += 4) {
        float wa = W[(k + 0) * HH + tid], wb = W[(k + 1) * HH + tid];
        float wc = W[(k + 2) * HH + tid], wd = W[(k + 3) * HH + tid];
#pragma unroll
        for (int t = 0; t < T; t++) {
            float4 v = *reinterpret_cast<const float4*>(&sIn[t * HH + k]);
            acc[t] = fmaf(v.x, wa, acc[t]); acc[t] = fmaf(v.y, wb, acc[t]);
            acc[t] = fmaf(v.z, wc, acc[t]); acc[t] = fmaf(v.w, wd, acc[t]);
        }
    }
#pragma unroll
    for (int t = 0; t < T; t++) {
        float v = acc[t];
        if (RELU) v = fmaxf(v, 0.f);
        out[(n0 + t) * HH + tid] = v;
    }
}

// ---------------- launch ----------------
extern "C" void kernel_launch(void* const* d_in, const int* in_sizes, int n_in,
                              void* d_out, int out_size)
{
    // logical tensor order: x,mask,eattr,eidx, m_w1,m_b1,m_w2,m_b2,
    // ea0_w1,ea0_b1,ea0_w2,ea0_b2, tag0_w,tag0_b, ea1_w1,ea1_b1,ea1_w2,ea1_b2,
    // tag1_w,tag1_b, ea2_w1,ea2_b1,ea2_w2,ea2_b2
    static const int ESZ[24] = {
        320000, 320000, 2560000, 320000,
        2048, 128, 2048, 16,
        6144, 128, 16384, 128,
        65536, 128,
        34816, 128, 16384, 128,
        65536, 128,
        34816, 128, 2048, 16};
    static const int M_DICT[24] = {0,1,2,3,4,5,6,7,8,9,10,11,12,13,14,15,16,17,18,19,20,21,22,23};
    static const int M_SIG[24]  = {0,1,2,23,3,4,5,6,7,8,9,10,11,12,13,14,15,16,17,18,19,20,21,22};
    static const int M_ALPHA[24]= {23,18,12,13,16,14,17,15,2,0,3,1,20,19,6,4,7,5,22,21,10,8,11,9};
    const int* cands[3] = {M_DICT, M_SIG, M_ALPHA};
    const int* map = M_DICT;
    for (int ci = 0; ci < 3; ci++) {
        bool ok = (n_in >= 24);
        for (int l = 0; l < 24 && ok; l++) ok = (in_sizes[cands[ci][l]] == ESZ[l]);
        if (ok) { map = cands[ci]; break; }
    }
#define INP(l) ((const float*)d_in[map[l]])
    const float* x     = INP(0);
    const float* mask  = INP(1);
    const float* eattr = INP(2);
    const int*   ei    = (const int*)d_in[map[3]];
    const float *m_w1 = INP(4), *m_b1 = INP(5), *m_w2 = INP(6), *m_b2 = INP(7);
    const float *ea0w1 = INP(8), *ea0b1 = INP(9), *ea0w2 = INP(10), *ea0b2 = INP(11);
    const float *tag0w = INP(12), *tag0b = INP(13);
    const float *ea1w1 = INP(14), *ea1b1 = INP(15), *ea1w2 = INP(16), *ea1b2 = INP(17);
    const float *tag1w = INP(18), *tag1b = INP(19);
    const float *ea2w1 = INP(20), *ea2b1 = INP(21), *ea2w2 = INP(22), *ea2b2 = INP(23);
#undef INP
    float* out = (float*)d_out;
    (void)out_size;

    // graph structure
    k_zero<<<(NNODE + 255) / 256, 256>>>();
    k_hist<<<E2 / 256, 256>>>(ei);
    k_scan<<<1, 1024>>>();
    k_scatter<<<E2 / 256, 256>>>(ei);

    // node embedding
    k_maskmlp<<<NNODE / 16, 128>>>(x, mask, m_w1, m_b1, m_w2, m_b2);

    // EA0 (h0[16] -> 128) + relu agg -> buf0
    k_ea_msg<NF, HH><<<E2 / 32, 128>>>(0, eattr, ei, ea0w1, ea0b1, ea0w2, ea0b2);
    k_agg<HH, true><<<NNODE, 128>>>(nullptr, 0);

    // TAG0: in buf0 -> out buf3 (relu)
    k_gemm<true,  false><<<NNODE / 16, 128>>>(0, tag0w,              tag0b, 3);
    k_hop<<<NNODE, 128>>>(0, 1);
    k_gemm<false, false><<<NNODE / 16, 128>>>(1, tag0w + 1 * HH * HH, tag0b, 3);
    k_hop<<<NNODE, 128>>>(1, 2);
    k_gemm<false, false><<<NNODE / 16, 128>>>(2, tag0w + 2 * HH * HH, tag0b, 3);
    k_hop<<<NNODE, 128>>>(2, 1);
    k_gemm<false, true ><<<NNODE / 16, 128>>>(1, tag0w + 3 * HH * HH, tag0b, 3);

    // EA1 (buf3 -> 128) + relu agg -> buf0
    k_ea_msg<HH, HH><<<E2 / 32, 128>>>(3, eattr, ei, ea1w1, ea1b1, ea1w2, ea1b2);
    k_agg<HH, true><<<NNODE, 128>>>(nullptr, 0);

    // TAG1: in buf0 -> out buf3 (relu)
    k_gemm<true,  false><<<NNODE / 16, 128>>>(0, tag1w,              tag1b, 3);
    k_hop<<<NNODE, 128>>>(0, 1);
    k_gemm<false, false><<<NNODE / 16, 128>>>(1, tag1w + 1 * HH * HH, tag1b, 3);
    k_hop<<<NNODE, 128>>>(1, 2);
    k_gemm<false, false><<<NNODE / 16, 128>>>(2, tag1w + 2 * HH * HH, tag1b, 3);
    k_hop<<<NNODE, 128>>>(2, 1);
    k_gemm<false, true ><<<NNODE / 16, 128>>>(1, tag1w + 3 * HH * HH, tag1b, 3);

    // EA2 (buf3 -> 16) + agg (no relu) -> d_out
    k_ea_msg<HH, 16><<<E2 / 32, 128>>>(3, eattr, ei, ea2w1, ea2b1, ea2w2, ea2b2);
    k_agg<16, false><<<NNODE / 8, 128>>>(out, 0);
}

// round 3
// speedup vs baseline: 1.0006x; 1.0006x over previous
#include <cuda_runtime.h>
#include <math.h>

#define NNODE 20000
#define NEDGE 160000
#define E2    320000
#define HH    128
#define NF    16
#define EF    16

// ---------------- device scratch (no allocations allowed) ----------------
__device__ int   g_deg[NNODE];
__device__ int   g_rowoff[NNODE];
__device__ int   g_cursor[NNODE];
__device__ float g_dis[NNODE];
__device__ int   g_csr_src[E2];
__device__ int   g_csr_eid[E2];
__device__ float g_h0[NNODE * NF];
__device__ float g_nb[4][NNODE * HH];          // node-feature ping-pong buffers
__device__ float g_msg[(size_t)E2 * HH];       // edge message buffer (164 MB)

__device__ __forceinline__ float* nodebuf(int s) { return g_nb[s]; }

// ---------------- graph structure build ----------------
__global__ void k_zero() {
    int i = blockIdx.x * 256 + threadIdx.x;
    if (i < NNODE) g_deg[i] = 0;
}

__global__ void k_hist(const int* __restrict__ ei) {
    int e = blockIdx.x * 256 + threadIdx.x;
    if (e >= E2) return;
    int d = (e < NEDGE) ? ei[NEDGE + e] : ei[e - NEDGE];
    atomicAdd(&g_deg[d], 1);
}

// single-block exclusive scan over degrees; also rsqrt norm + cursor init
__global__ void k_scan() {
    __shared__ int s[1024];
    __shared__ int carry;
    int t = threadIdx.x;
    if (t == 0) carry = 0;
    __syncthreads();
    for (int base = 0; base < NNODE; base += 1024) {
        int i = base + t;
        int v = (i < NNODE) ? g_deg[i] : 0;
        int cprev = carry;
        s[t] = v;
        __syncthreads();
        for (int off = 1; off < 1024; off <<= 1) {
            int add = (t >= off) ? s[t - off] : 0;
            __syncthreads();
            s[t] += add;
            __syncthreads();
        }
        if (i < NNODE) {
            int excl = s[t] - v + cprev;
            g_rowoff[i] = excl;
            g_cursor[i] = excl;
            g_dis[i] = (v > 0) ? rsqrtf((float)v) : 0.f;
        }
        __syncthreads();
        if (t == 0) carry = cprev + s[1023];
        __syncthreads();
    }
}

__global__ void k_scatter(const int* __restrict__ ei) {
    int e = blockIdx.x * 256 + threadIdx.x;
    if (e >= E2) return;
    int srcv = ei[e];  // works for both halves: [0,E)=src row, [E,2E)=dst row reversed
    int d = (e < NEDGE) ? ei[NEDGE + e] : ei[e - NEDGE];
    int slot = atomicAdd(&g_cursor[d], 1);
    g_csr_src[slot] = srcv;
    g_csr_eid[slot] = e;
}

// ---------------- mask MLP + residual: g_h0 = mlp2(mask) + x ----------------
__global__ void __launch_bounds__(128) k_maskmlp(
    const float* __restrict__ x, const float* __restrict__ mask,
    const float* __restrict__ w1, const float* __restrict__ b1,
    const float* __restrict__ w2, const float* __restrict__ b2)
{
    constexpr int T = 16;
    __shared__ __align__(16) float sM[T * NF];
    __shared__ __align__(16) float sH[T * HH];
    int tid = threadIdx.x;
    int n0 = blockIdx.x * T;
    for (int o = tid; o < T * NF; o += 128) sM[o] = mask[n0 * NF + o];
    __syncthreads();

    float acc[T];
    float bj = b1[tid];
#pragma unroll
    for (int t = 0; t < T; t++) acc[t] = bj;
#pragma unroll
    for (int i = 0; i < NF; i += 4) {
        float wa = w1[(i + 0) * HH + tid], wb = w1[(i + 1) * HH + tid];
        float wc = w1[(i + 2) * HH + tid], wd = w1[(i + 3) * HH + tid];
#pragma unroll
        for (int t = 0; t < T; t++) {
            float4 v = *reinterpret_cast<const float4*>(&sM[t * NF + i]);
            acc[t] = fmaf(v.x, wa, acc[t]); acc[t] = fmaf(v.y, wb, acc[t]);
            acc[t] = fmaf(v.z, wc, acc[t]); acc[t] = fmaf(v.w, wd, acc[t]);
        }
    }
#pragma unroll
    for (int t = 0; t < T; t++) sH[t * HH + tid] = fmaxf(acc[t], 0.f);
    __syncthreads();

    for (int o = tid; o < T * NF; o += 128) {
        int t = o >> 4, c = o & 15;
        float v = b2[c];
#pragma unroll 1
        for (int k = 0; k < HH; k += 4) {
            float4 h = *reinterpret_cast<const float4*>(&sH[t * HH + k]);
            v = fmaf(h.x, w2[(k + 0) * NF + c], v);
            v = fmaf(h.y, w2[(k + 1) * NF + c], v);
            v = fmaf(h.z, w2[(k + 2) * NF + c], v);
            v = fmaf(h.w, w2[(k + 3) * NF + c], v);
        }
        g_h0[n0 * NF + o] = v + x[n0 * NF + o];
    }
}

// ---------------- fused edge MLP: msg[e] = relu(cat @ W1 + b1) @ W2 + b2 ----------------
template <int DH, int DOUT>
__global__ void __launch_bounds__(128) k_ea_msg(
    int hsel,
    const float* __restrict__ eattr, const int* __restrict__ ei,
    const float* __restrict__ w1, const float* __restrict__ b1,
    const float* __restrict__ w2, const float* __restrict__ b2)
{
    constexpr int T = 32;
    constexpr int DIN = 2 * DH + EF;
    constexpr int IN_F  = T * DIN;
    constexpr int HID_F = T * HH;
    constexpr int RED_F = (DOUT == 16) ? 8 * T * 16 : 0;
    constexpr int SM_F  = (IN_F > HID_F + RED_F) ? IN_F : (HID_F + RED_F);
    __shared__ __align__(16) float sm[SM_F];
    __shared__ int sSrc[T], sDst[T], sEa[T];

    const float* hfeat = (DH == NF) ? g_h0 : nodebuf(hsel);
    int tid = threadIdx.x;
    int e0 = blockIdx.x * T;
    if (tid < T) {
        int e = e0 + tid;
        sSrc[tid] = ei[e];
        sDst[tid] = (e < NEDGE) ? ei[NEDGE + e] : ei[e - NEDGE];
        sEa[tid]  = (e < NEDGE) ? e : e - NEDGE;
    }
    __syncthreads();

    // stage concatenated inputs
#pragma unroll 1
    for (int t = 0; t < T; t++) {
        int d = sDst[t], s = sSrc[t], er = sEa[t];
        for (int p = tid; p < DIN; p += 128) {
            float v;
            if (p < DH)           v = hfeat[d * DH + p];
            else if (p < 2 * DH)  v = hfeat[s * DH + (p - DH)];
            else                  v = eattr[er * EF + (p - 2 * DH)];
            sm[t * DIN + p] = v;
        }
    }
    __syncthreads();

    // hidden = relu(in @ W1 + b1); thread j owns hidden column j for 32 edges
    int j = tid;
    float acc[T];
    float bj = b1[j];
#pragma unroll
    for (int t = 0; t < T; t++) acc[t] = bj;
#pragma unroll 1
    for (int i = 0; i < DIN; i += 4) {
        float wa = w1[(i + 0) * HH + j], wb = w1[(i + 1) * HH + j];
        float wc = w1[(i + 2) * HH + j], wd = w1[(i + 3) * HH + j];
#pragma unroll
        for (int t = 0; t < T; t++) {
            float4 v = *reinterpret_cast<const float4*>(&sm[t * DIN + i]);
            acc[t] = fmaf(v.x, wa, acc[t]); acc[t] = fmaf(v.y, wb, acc[t]);
            acc[t] = fmaf(v.z, wc, acc[t]); acc[t] = fmaf(v.w, wd, acc[t]);
        }
    }
    __syncthreads();               // all reads of input region done
    float* shid = sm;              // hidden aliases the input region
#pragma unroll
    for (int t = 0; t < T; t++) shid[t * HH + j] = fmaxf(acc[t], 0.f);
    __syncthreads();

    if (DOUT == HH) {
        float cj = b2[j];
#pragma unroll
        for (int t = 0; t < T; t++) acc[t] = cj;
#pragma unroll 1
        for (int k = 0; k < HH; k += 4) {
            float wa = w2[(k + 0) * HH + j], wb = w2[(k + 1) * HH + j];
            float wc = w2[(k + 2) * HH + j], wd = w2[(k + 3) * HH + j];
#pragma unroll
            for (int t = 0; t < T; t++) {
                float4 v = *reinterpret_cast<const float4*>(&shid[t * HH + k]);
                acc[t] = fmaf(v.x, wa, acc[t]); acc[t] = fmaf(v.y, wb, acc[t]);
                acc[t] = fmaf(v.z, wc, acc[t]); acc[t] = fmaf(v.w, wd, acc[t]);
            }
        }
#pragma unroll
        for (int t = 0; t < T; t++) g_msg[(size_t)(e0 + t) * HH + j] = acc[t];
    } else {
        // DOUT = 16: split-K across 8 thread groups of 16
        int c = tid & 15;
        int seg = tid >> 4;
        float pacc[T];
#pragma unroll
        for (int t = 0; t < T; t++) pacc[t] = 0.f;
#pragma unroll 1
        for (int k = seg * 16; k < seg * 16 + 16; k += 4) {
            float wa = w2[(k + 0) * 16 + c], wb = w2[(k + 1) * 16 + c];
            float wc = w2[(k + 2) * 16 + c], wd = w2[(k + 3) * 16 + c];
#pragma unroll
            for (int t = 0; t < T; t++) {
                float4 v = *reinterpret_cast<const float4*>(&shid[t * HH + k]);
                pacc[t] = fmaf(v.x, wa, pacc[t]); pacc[t] = fmaf(v.y, wb, pacc[t]);
                pacc[t] = fmaf(v.z, wc, pacc[t]); pacc[t] = fmaf(v.w, wd, pacc[t]);
            }
        }
        float* sred = sm + HID_F;
#pragma unroll
        for (int t = 0; t < T; t++) sred[(seg * T + t) * 16 + c] = pacc[t];
        __syncthreads();
        for (int o = tid; o < T * 16; o += 128) {
            int t = o >> 4, cc = o & 15;
            float v = b2[cc];
#pragma unroll
            for (int s2 = 0; s2 < 8; s2++) v += sred[(s2 * T + t) * 16 + cc];
            g_msg[(size_t)(e0 + t) * 16 + cc] = v;
        }
    }
}

// ---------------- CSR segment-sum of messages ----------------
template <int DOUT, bool RELU>
__global__ void k_agg(float* __restrict__ outp, int outsel) {
    constexpr int PER = 128 / DOUT;
    int tid = threadIdx.x;
    int n = blockIdx.x * PER + tid / DOUT;
    int j = tid % DOUT;
    if (n >= NNODE) return;
    float* out = outp ? outp : nodebuf(outsel);
    int beg = g_rowoff[n], len = g_deg[n];
    float acc = 0.f;
    for (int i = 0; i < len; i++) {
        int eid = g_csr_eid[beg + i];
        acc += g_msg[(size_t)eid * DOUT + j];
    }
    if (RELU) acc = fmaxf(acc, 0.f);
    out[n * DOUT + j] = acc;
}

// ---------------- TAG propagation hop: out[n] = dis[n] * sum dis[s] * h[s] ----------------
__global__ void k_hop(int insel, int outsel) {
    const float* hin = nodebuf(insel);
    float* hout = nodebuf(outsel);
    int n = blockIdx.x, j = threadIdx.x;
    int beg = g_rowoff[n], len = g_deg[n];
    float acc = 0.f;
    for (int i = 0; i < len; i++) {
        int s = g_csr_src[beg + i];
        acc = fmaf(g_dis[s], hin[s * HH + j], acc);
    }
    hout[n * HH + j] = g_dis[n] * acc;
}

// ---------------- node GEMM: out (=bias | +=) in @ W, optional relu ----------------
template <bool INIT, bool RELU>
__global__ void __launch_bounds__(128) k_gemm(
    int insel, const float* __restrict__ W, const float* __restrict__ bias, int outsel)
{
    constexpr int T = 16;
    __shared__ __align__(16) float sIn[T * HH];
    const float* in = nodebuf(insel);
    float* out = nodebuf(outsel);
    int tid = threadIdx.x;
    int n0 = blockIdx.x * T;
#pragma unroll
    for (int t = 0; t < T; t++) sIn[t * HH + tid] = in[(n0 + t) * HH + tid];
    __syncthreads();
    float acc[T];
    if (INIT) {
        float b = bias[tid];
#pragma unroll
        for (int t = 0; t < T; t++) acc[t] = b;
    } else {
#pragma unroll
        for (int t = 0; t < T; t++) acc[t] = out[(n0 + t) * HH + tid];
    }
#pragma unroll 1
    for (int k = 0; k < HH; k += 4) {
        float wa = W[(k + 0) * HH + tid], wb = W[(k + 1) * HH + tid];
        float wc = W[(k + 2) * HH + tid], wd = W[(k + 3) * HH + tid];
#pragma unroll
        for (int t = 0; t < T; t++) {
            float4 v = *reinterpret_cast<const float4*>(&sIn[t * HH + k]);
            acc[t] = fmaf(v.x, wa, acc[t]); acc[t] = fmaf(v.y, wb, acc[t]);
            acc[t] = fmaf(v.z, wc, acc[t]); acc[t] = fmaf(v.w, wd, acc[t]);
        }
    }
#pragma unroll
    for (int t = 0; t < T; t++) {
        float v = acc[t];
        if (RELU) v = fmaxf(v, 0.f);
        out[(n0 + t) * HH + tid] = v;
    }
}

// ---------------- launch ----------------
extern "C" void kernel_launch(void* const* d_in, const int* in_sizes, int n_in,
                              void* d_out, int out_size)
{
    // logical tensor order: x,mask,eattr,eidx, m_w1,m_b1,m_w2,m_b2,
    // ea0_w1,ea0_b1,ea0_w2,ea0_b2, tag0_w,tag0_b, ea1_w1,ea1_b1,ea1_w2,ea1_b2,
    // tag1_w,tag1_b, ea2_w1,ea2_b1,ea2_w2,ea2_b2
    static const int ESZ[24] = {
        320000, 320000, 2560000, 320000,
        2048, 128, 2048, 16,
        6144, 128, 16384, 128,
        65536, 128,
        34816, 128, 16384, 128,
        65536, 128,
        34816, 128, 2048, 16};
    static const int M_DICT[24] = {0,1,2,3,4,5,6,7,8,9,10,11,12,13,14,15,16,17,18,19,20,21,22,23};
    static const int M_SIG[24]  = {0,1,2,23,3,4,5,6,7,8,9,10,11,12,13,14,15,16,17,18,19,20,21,22};
    static const int M_ALPHA[24]= {23,18,12,13,16,14,17,15,2,0,3,1,20,19,6,4,7,5,22,21,10,8,11,9};
    const int* cands[3] = {M_DICT, M_SIG, M_ALPHA};
    const int* map = M_DICT;
    for (int ci = 0; ci < 3; ci++) {
        bool ok = (n_in >= 24);
        for (int l = 0; l < 24 && ok; l++) ok = (in_sizes[cands[ci][l]] == ESZ[l]);
        if (ok) { map = cands[ci]; break; }
    }
#define INP(l) ((const float*)d_in[map[l]])
    const float* x     = INP(0);
    const float* mask  = INP(1);
    const float* eattr = INP(2);
    const int*   ei    = (const int*)d_in[map[3]];
    const float *m_w1 = INP(4), *m_b1 = INP(5), *m_w2 = INP(6), *m_b2 = INP(7);
    const float *ea0w1 = INP(8), *ea0b1 = INP(9), *ea0w2 = INP(10), *ea0b2 = INP(11);
    const float *tag0w = INP(12), *tag0b = INP(13);
    const float *ea1w1 = INP(14), *ea1b1 = INP(15), *ea1w2 = INP(16), *ea1b2 = INP(17);
    const float *tag1w = INP(18), *tag1b = INP(19);
    const float *ea2w1 = INP(20), *ea2b1 = INP(21), *ea2w2 = INP(22), *ea2b2 = INP(23);
#undef INP
    float* out = (float*)d_out;
    (void)out_size;

    // graph structure
    k_zero<<<(NNODE + 255) / 256, 256>>>();
    k_hist<<<E2 / 256, 256>>>(ei);
    k_scan<<<1, 1024>>>();
    k_scatter<<<E2 / 256, 256>>>(ei);

    // node embedding
    k_maskmlp<<<NNODE / 16, 128>>>(x, mask, m_w1, m_b1, m_w2, m_b2);

    // EA0 (h0[16] -> 128) + relu agg -> buf0
    k_ea_msg<NF, HH><<<E2 / 32, 128>>>(0, eattr, ei, ea0w1, ea0b1, ea0w2, ea0b2);
    k_agg<HH, true><<<NNODE, 128>>>(nullptr, 0);

    // TAG0: in buf0 -> out buf3 (relu)
    k_gemm<true,  false><<<NNODE / 16, 128>>>(0, tag0w,              tag0b, 3);
    k_hop<<<NNODE, 128>>>(0, 1);
    k_gemm<false, false><<<NNODE / 16, 128>>>(1, tag0w + 1 * HH * HH, tag0b, 3);
    k_hop<<<NNODE, 128>>>(1, 2);
    k_gemm<false, false><<<NNODE / 16, 128>>>(2, tag0w + 2 * HH * HH, tag0b, 3);
    k_hop<<<NNODE, 128>>>(2, 1);
    k_gemm<false, true ><<<NNODE / 16, 128>>>(1, tag0w + 3 * HH * HH, tag0b, 3);

    // EA1 (buf3 -> 128) + relu agg -> buf0
    k_ea_msg<HH, HH><<<E2 / 32, 128>>>(3, eattr, ei, ea1w1, ea1b1, ea1w2, ea1b2);
    k_agg<HH, true><<<NNODE, 128>>>(nullptr, 0);

    // TAG1: in buf0 -> out buf3 (relu)
    k_gemm<true,  false><<<NNODE / 16, 128>>>(0, tag1w,              tag1b, 3);
    k_hop<<<NNODE, 128>>>(0, 1);
    k_gemm<false, false><<<NNODE / 16, 128>>>(1, tag1w + 1 * HH * HH, tag1b, 3);
    k_hop<<<NNODE, 128>>>(1, 2);
    k_gemm<false, false><<<NNODE / 16, 128>>>(2, tag1w + 2 * HH * HH, tag1b, 3);
    k_hop<<<NNODE, 128>>>(2, 1);
    k_gemm<false, true ><<<NNODE / 16, 128>>>(1, tag1w + 3 * HH * HH, tag1b, 3);

    // EA2 (buf3 -> 16) + agg (no relu) -> d_out
    k_ea_msg<HH, 16><<<E2 / 32, 128>>>(3, eattr, ei, ea2w1, ea2b1, ea2w2, ea2b2);
    k_agg<16, false><<<NNODE / 8, 128>>>(out, 0);
}

// round 4
// speedup vs baseline: 3.3581x; 3.3562x over previous
#include <cuda_runtime.h>
#include <math.h>

#define NNODE 20000
#define NEDGE 160000
#define E2    320000
#define HH    128
#define NF    16
#define EF    16

// ---------------- device scratch (no allocations allowed) ----------------
__device__ int   g_deg[NNODE];
__device__ int   g_rowoff[NNODE];
__device__ int   g_cursor[NNODE];
__device__ float g_dis[NNODE];
__device__ int   g_csr_src[E2];
__device__ int   g_csr_ea[E2];                 // eattr index (0..NEDGE)
__device__ float g_h0[NNODE * NF];
__device__ float g_nb[5][NNODE * HH];          // node-feature buffers
__device__ float g_msg[(size_t)NEDGE * HH];    // per-unique-edge C buffer (82 MB)

__device__ __forceinline__ const float* sel_in(int s, const float* ext) {
    if (s >= 0) return g_nb[s];
    if (s == -3) return g_h0;
    return ext;
}
__device__ __forceinline__ float* sel_out(int s, float* ext) {
    if (s >= 0) return g_nb[s];
    if (s == -2) return g_msg;
    return ext;
}

// ---------------- graph structure build ----------------
__global__ void k_zero() {
    int i = blockIdx.x * 256 + threadIdx.x;
    if (i < NNODE) g_deg[i] = 0;
}

__global__ void k_hist(const int* __restrict__ ei) {
    int e = blockIdx.x * 256 + threadIdx.x;
    if (e >= E2) return;
    int d = (e < NEDGE) ? ei[NEDGE + e] : ei[e - NEDGE];
    atomicAdd(&g_deg[d], 1);
}

// single-block exclusive scan over degrees; also rsqrt norm + cursor init
__global__ void k_scan() {
    __shared__ int s[1024];
    __shared__ int carry;
    int t = threadIdx.x;
    if (t == 0) carry = 0;
    __syncthreads();
    for (int base = 0; base < NNODE; base += 1024) {
        int i = base + t;
        int v = (i < NNODE) ? g_deg[i] : 0;
        int cprev = carry;
        s[t] = v;
        __syncthreads();
        for (int off = 1; off < 1024; off <<= 1) {
            int add = (t >= off) ? s[t - off] : 0;
            __syncthreads();
            s[t] += add;
            __syncthreads();
        }
        if (i < NNODE) {
            int excl = s[t] - v + cprev;
            g_rowoff[i] = excl;
            g_cursor[i] = excl;
            g_dis[i] = (v > 0) ? rsqrtf((float)v) : 0.f;
        }
        __syncthreads();
        if (t == 0) carry = cprev + s[1023];
        __syncthreads();
    }
}

__global__ void k_scatter(const int* __restrict__ ei) {
    int e = blockIdx.x * 256 + threadIdx.x;
    if (e >= E2) return;
    int srcv = ei[e];  // both halves: [0,E)=src row, [E,2E)=dst row reversed
    int d  = (e < NEDGE) ? ei[NEDGE + e] : ei[e - NEDGE];
    int ea = (e < NEDGE) ? e : e - NEDGE;
    int slot = atomicAdd(&g_cursor[d], 1);
    g_csr_src[slot] = srcv;
    g_csr_ea[slot]  = ea;
}

// ---------------- mask MLP + residual: g_h0 = mlp2(mask) + x ----------------
__global__ void __launch_bounds__(128) k_maskmlp(
    const float* __restrict__ x, const float* __restrict__ mask,
    const float* __restrict__ w1, const float* __restrict__ b1,
    const float* __restrict__ w2, const float* __restrict__ b2)
{
    constexpr int T = 16;
    __shared__ __align__(16) float sM[T * NF];
    __shared__ __align__(16) float sH[T * HH];
    int tid = threadIdx.x;
    int n0 = blockIdx.x * T;
    for (int o = tid; o < T * NF; o += 128) sM[o] = mask[n0 * NF + o];
    __syncthreads();

    float acc[T];
    float bj = b1[tid];
#pragma unroll
    for (int t = 0; t < T; t++) acc[t] = bj;
#pragma unroll
    for (int i = 0; i < NF; i += 4) {
        float wa = w1[(i + 0) * HH + tid], wb = w1[(i + 1) * HH + tid];
        float wc = w1[(i + 2) * HH + tid], wd = w1[(i + 3) * HH + tid];
#pragma unroll
        for (int t = 0; t < T; t++) {
            float4 v = *reinterpret_cast<const float4*>(&sM[t * NF + i]);
            acc[t] = fmaf(v.x, wa, acc[t]); acc[t] = fmaf(v.y, wb, acc[t]);
            acc[t] = fmaf(v.z, wc, acc[t]); acc[t] = fmaf(v.w, wd, acc[t]);
        }
    }
#pragma unroll
    for (int t = 0; t < T; t++) sH[t * HH + tid] = fmaxf(acc[t], 0.f);
    __syncthreads();

    for (int o = tid; o < T * NF; o += 128) {
        int t = o >> 4, c = o & 15;
        float v = b2[c];
#pragma unroll 1
        for (int k = 0; k < HH; k += 4) {
            float4 h = *reinterpret_cast<const float4*>(&sH[t * HH + k]);
            v = fmaf(h.x, w2[(k + 0) * NF + c], v);
            v = fmaf(h.y, w2[(k + 1) * NF + c], v);
            v = fmaf(h.z, w2[(k + 2) * NF + c], v);
            v = fmaf(h.w, w2[(k + 3) * NF + c], v);
        }
        g_h0[n0 * NF + o] = v + x[n0 * NF + o];
    }
}

// ---------------- generic GEMM: out[M,128] = op(in[M,K] @ W[K,128]) ----------------
// BIASMODE: 0 = zero-init, 1 = +bias, 2 = +deg[n]*bias. ACCUM: out += result.
template <int K, int BIASMODE, bool RELU, bool ACCUM>
__global__ void __launch_bounds__(128) k_mm(
    int insel, const float* __restrict__ in_ext,
    int outsel, float* __restrict__ out_ext,
    const float* __restrict__ W, const float* __restrict__ bias)
{
    constexpr int T = 16;
    __shared__ __align__(16) float sIn[T * K];
    const float* in = sel_in(insel, in_ext);
    float* out = sel_out(outsel, out_ext);
    int tid = threadIdx.x;
    int n0 = blockIdx.x * T;

    for (int o = tid; o < T * K; o += 128) sIn[o] = in[n0 * K + o];
    __syncthreads();

    float acc[T];
    if (ACCUM) {
#pragma unroll
        for (int t = 0; t < T; t++) acc[t] = out[(n0 + t) * HH + tid];
    } else if (BIASMODE == 1) {
        float b = bias[tid];
#pragma unroll
        for (int t = 0; t < T; t++) acc[t] = b;
    } else if (BIASMODE == 2) {
        float b = bias[tid];
#pragma unroll
        for (int t = 0; t < T; t++) acc[t] = b * (float)g_deg[n0 + t];
    } else {
#pragma unroll
        for (int t = 0; t < T; t++) acc[t] = 0.f;
    }

#pragma unroll 1
    for (int k = 0; k < K; k += 4) {
        float wa = W[(k + 0) * HH + tid], wb = W[(k + 1) * HH + tid];
        float wc = W[(k + 2) * HH + tid], wd = W[(k + 3) * HH + tid];
#pragma unroll
        for (int t = 0; t < T; t++) {
            float4 v = *reinterpret_cast<const float4*>(&sIn[t * K + k]);
            acc[t] = fmaf(v.x, wa, acc[t]); acc[t] = fmaf(v.y, wb, acc[t]);
            acc[t] = fmaf(v.z, wc, acc[t]); acc[t] = fmaf(v.w, wd, acc[t]);
        }
    }
#pragma unroll
    for (int t = 0; t < T; t++) {
        float v = acc[t];
        if (RELU) v = fmaxf(v, 0.f);
        out[(n0 + t) * HH + tid] = v;
    }
}

// ---------------- fused hidden + aggregation ----------------
// S[n] = sum over incident edges of relu(A[n] + B[src] + C[ea])
// (A = x_dst@W1a + b1, B = x_src@W1b, C = eattr@W1c -- layer-1 decomposition;
//  the layer-2 GEMM commutes with the segment-sum and is applied per node after.)
__global__ void k_fused_agg() {
    const float* __restrict__ A = g_nb[0];
    const float* __restrict__ B = g_nb[1];
    float* __restrict__ S = g_nb[2];
    int n = blockIdx.x, j = threadIdx.x;
    int beg = g_rowoff[n], len = g_deg[n];
    float a = A[n * HH + j];
    float acc = 0.f;
    for (int i = 0; i < len; i++) {
        int s  = g_csr_src[beg + i];
        int ea = g_csr_ea[beg + i];
        acc += fmaxf(a + B[s * HH + j] + g_msg[(size_t)ea * HH + j], 0.f);
    }
    S[n * HH + j] = acc;
}

// ---------------- TAG propagation hop: out[n] = dis[n] * sum dis[s] * h[s] ----------------
__global__ void k_hop(int insel, int outsel) {
    const float* hin = g_nb[insel];
    float* hout = g_nb[outsel];
    int n = blockIdx.x, j = threadIdx.x;
    int beg = g_rowoff[n], len = g_deg[n];
    float acc = 0.f;
    for (int i = 0; i < len; i++) {
        int s = g_csr_src[beg + i];
        acc = fmaf(g_dis[s], hin[s * HH + j], acc);
    }
    hout[n * HH + j] = g_dis[n] * acc;
}

// ---------------- final: out[n,16] = S[n]@W2[128,16] + deg[n]*b2 ----------------
__global__ void __launch_bounds__(128) k_out16(
    float* __restrict__ out, const float* __restrict__ W2, const float* __restrict__ b2)
{
    int tid = threadIdx.x;
    int n = blockIdx.x * 8 + (tid >> 4);
    int c = tid & 15;
    const float* S = g_nb[2];
    float acc = b2[c] * (float)g_deg[n];
#pragma unroll 4
    for (int k = 0; k < HH; k++)
        acc = fmaf(__ldg(&S[n * HH + k]), __ldg(&W2[k * 16 + c]), acc);
    out[n * 16 + c] = acc;
}

// ---------------- launch ----------------
extern "C" void kernel_launch(void* const* d_in, const int* in_sizes, int n_in,
                              void* d_out, int out_size)
{
    static const int ESZ[24] = {
        320000, 320000, 2560000, 320000,
        2048, 128, 2048, 16,
        6144, 128, 16384, 128,
        65536, 128,
        34816, 128, 16384, 128,
        65536, 128,
        34816, 128, 2048, 16};
    static const int M_DICT[24] = {0,1,2,3,4,5,6,7,8,9,10,11,12,13,14,15,16,17,18,19,20,21,22,23};
    static const int M_SIG[24]  = {0,1,2,23,3,4,5,6,7,8,9,10,11,12,13,14,15,16,17,18,19,20,21,22};
    static const int M_ALPHA[24]= {23,18,12,13,16,14,17,15,2,0,3,1,20,19,6,4,7,5,22,21,10,8,11,9};
    const int* cands[3] = {M_DICT, M_SIG, M_ALPHA};
    const int* map = M_DICT;
    for (int ci = 0; ci < 3; ci++) {
        bool ok = (n_in >= 24);
        for (int l = 0; l < 24 && ok; l++) ok = (in_sizes[cands[ci][l]] == ESZ[l]);
        if (ok) { map = cands[ci]; break; }
    }
#define INP(l) ((const float*)d_in[map[l]])
    const float* x     = INP(0);
    const float* mask  = INP(1);
    const float* eattr = INP(2);
    const int*   ei    = (const int*)d_in[map[3]];
    const float *m_w1 = INP(4), *m_b1 = INP(5), *m_w2 = INP(6), *m_b2 = INP(7);
    const float *ea0w1 = INP(8), *ea0b1 = INP(9), *ea0w2 = INP(10), *ea0b2 = INP(11);
    const float *tag0w = INP(12), *tag0b = INP(13);
    const float *ea1w1 = INP(14), *ea1b1 = INP(15), *ea1w2 = INP(16), *ea1b2 = INP(17);
    const float *tag1w = INP(18), *tag1b = INP(19);
    const float *ea2w1 = INP(20), *ea2b1 = INP(21), *ea2w2 = INP(22), *ea2b2 = INP(23);
#undef INP
    float* out = (float*)d_out;
    (void)out_size;

    const int GN  = NNODE / 16;   // 1250 node-GEMM blocks
    const int GE  = NEDGE / 16;   // 10000 edge-C blocks

    // graph structure
    k_zero<<<(NNODE + 255) / 256, 256>>>();
    k_hist<<<E2 / 256, 256>>>(ei);
    k_scan<<<1, 1024>>>();
    k_scatter<<<E2 / 256, 256>>>(ei);

    // node embedding
    k_maskmlp<<<GN, 128>>>(x, mask, m_w1, m_b1, m_w2, m_b2);

    // ---- EA0 (h0[16] -> 128), input g_h0 (sel -3), output nb3 ----
    k_mm<16, 1, false, false><<<GN, 128>>>(-3, nullptr, 0, nullptr, ea0w1,               ea0b1);
    k_mm<16, 0, false, false><<<GN, 128>>>(-3, nullptr, 1, nullptr, ea0w1 + 16 * HH,     nullptr);
    k_mm<16, 0, false, false><<<GE, 128>>>(-1, eattr,  -2, nullptr, ea0w1 + 32 * HH,     nullptr);
    k_fused_agg<<<NNODE, 128>>>();
    k_mm<128, 2, true, false><<<GN, 128>>>(2, nullptr, 3, nullptr, ea0w2, ea0b2);

    // ---- TAG0: in nb3 -> out nb4 (relu), tmps nb0/nb1 ----
    k_mm<128, 1, false, false><<<GN, 128>>>(3, nullptr, 4, nullptr, tag0w,               tag0b);
    k_hop<<<NNODE, 128>>>(3, 0);
    k_mm<128, 0, false, true ><<<GN, 128>>>(0, nullptr, 4, nullptr, tag0w + 1 * HH * HH, nullptr);
    k_hop<<<NNODE, 128>>>(0, 1);
    k_mm<128, 0, false, true ><<<GN, 128>>>(1, nullptr, 4, nullptr, tag0w + 2 * HH * HH, nullptr);
    k_hop<<<NNODE, 128>>>(1, 0);
    k_mm<128, 0, true,  true ><<<GN, 128>>>(0, nullptr, 4, nullptr, tag0w + 3 * HH * HH, nullptr);

    // ---- EA1 (nb4 -> 128), output nb3 ----
    k_mm<128, 1, false, false><<<GN, 128>>>(4, nullptr, 0, nullptr, ea1w1,                ea1b1);
    k_mm<128, 0, false, false><<<GN, 128>>>(4, nullptr, 1, nullptr, ea1w1 + 128 * HH,     nullptr);
    k_mm<16,  0, false, false><<<GE, 128>>>(-1, eattr, -2, nullptr, ea1w1 + 256 * HH,     nullptr);
    k_fused_agg<<<NNODE, 128>>>();
    k_mm<128, 2, true, false><<<GN, 128>>>(2, nullptr, 3, nullptr, ea1w2, ea1b2);

    // ---- TAG1: in nb3 -> out nb4 (relu) ----
    k_mm<128, 1, false, false><<<GN, 128>>>(3, nullptr, 4, nullptr, tag1w,               tag1b);
    k_hop<<<NNODE, 128>>>(3, 0);
    k_mm<128, 0, false, true ><<<GN, 128>>>(0, nullptr, 4, nullptr, tag1w + 1 * HH * HH, nullptr);
    k_hop<<<NNODE, 128>>>(0, 1);
    k_mm<128, 0, false, true ><<<GN, 128>>>(1, nullptr, 4, nullptr, tag1w + 2 * HH * HH, nullptr);
    k_hop<<<NNODE, 128>>>(1, 0);
    k_mm<128, 0, true,  true ><<<GN, 128>>>(0, nullptr, 4, nullptr, tag1w + 3 * HH * HH, nullptr);

    // ---- EA2 (nb4 -> 16) -> d_out ----
    k_mm<128, 1, false, false><<<GN, 128>>>(4, nullptr, 0, nullptr, ea2w1,                ea2b1);
    k_mm<128, 0, false, false><<<GN, 128>>>(4, nullptr, 1, nullptr, ea2w1 + 128 * HH,     nullptr);
    k_mm<16,  0, false, false><<<GE, 128>>>(-1, eattr, -2, nullptr, ea2w1 + 256 * HH,     nullptr);
    k_fused_agg<<<NNODE, 128>>>();
    k_out16<<<NNODE / 8, 128>>>(out, ea2w2, ea2b2);
}